// round 1
// baseline (speedup 1.0000x reference)
#include <cuda_runtime.h>
#include <cstdint>

#define NBLK  1024
#define TPB   256
#define WPB   8          // warps per block
#define NBINS 15
#define NCOL  45         // 15 counts, 15 conf sums, 15 acc sums

// Scratch: per-block partials (column-major for coalesced reduction) + reduced bins.
__device__ double g_part[NCOL * NBLK];
__device__ double g_red[NCOL];

__device__ __forceinline__ float ex2f(float x) {
    float r; asm("ex2.approx.f32 %0, %1;" : "=f"(r) : "f"(x)); return r;
}

// searchsorted(linspace(0,1,16), conf, 'left') - 1, for conf in (0, 1].
// bin = #{ i in 1..14 : conf > b[i] }
__device__ __forceinline__ int bin_of(float conf) {
    int bin = 0;
#pragma unroll
    for (int i = 1; i <= NBINS - 1; i++)
        bin += (conf > (float)(i / 15.0)) ? 1 : 0;
    return bin;
}

// ---------------------------------------------------------------------------
// Main pass, specialized C=100. Layout: 4 lanes per row, 8 rows per warp.
// Lane (group g, sub q) loads float4 indices q, q+4, ..., q+20 (96 elems) plus
// scalar element 96+q  -> 25 floats per lane, row fully register-resident.
// ---------------------------------------------------------------------------
__global__ __launch_bounds__(TPB)
void ece_pass1_c100(const float* __restrict__ logits,
                    const int*   __restrict__ labels,
                    int N)
{
    const int tid  = threadIdx.x;
    const int lane = tid & 31;
    const int q    = lane & 3;          // sub-lane within row group
    const int grp  = lane >> 2;         // row group within warp (0..7)
    const int warpId = blockIdx.x * WPB + (tid >> 5);
    const int rowStride = NBLK * WPB * 8;   // 65536 rows per sweep

    const float L2E = 1.4426950408889634f;

    // Register histogram: lane q owns bins {q, q+4, q+8, q+12}
    float cnt[4]  = {0.f, 0.f, 0.f, 0.f};
    float csum[4] = {0.f, 0.f, 0.f, 0.f};
    float asum[4] = {0.f, 0.f, 0.f, 0.f};

    for (int base = warpId * 8; base < N; base += rowStride) {
        const int  row   = base + grp;
        const bool valid = (row < N);
        const int  rowl  = valid ? row : (N - 1);

        const float* rp  = logits + (size_t)rowl * 100;
        const float4* rp4 = reinterpret_cast<const float4*>(rp);

        float4 a0 = rp4[q];
        float4 a1 = rp4[q + 4];
        float4 a2 = rp4[q + 8];
        float4 a3 = rp4[q + 12];
        float4 a4 = rp4[q + 16];
        float4 a5 = rp4[q + 20];
        float  tl = rp[96 + q];

        // ---- pass 1: row max (group of 4 lanes) ----
        float m = tl;
#define MX4(a) m = fmaxf(m, fmaxf(fmaxf(a.x, a.y), fmaxf(a.z, a.w)))
        MX4(a0); MX4(a1); MX4(a2); MX4(a3); MX4(a4); MX4(a5);
#undef MX4
        m = fmaxf(m, __shfl_xor_sync(0xffffffffu, m, 1));
        m = fmaxf(m, __shfl_xor_sync(0xffffffffu, m, 2));

        // ---- pass 2: sum exp(v - m) and first-occurrence argmax ----
        const float mb = m * L2E;
        float s = 0.f;
        int am = 0x7fffffff;
        const int ib = 4 * q;
#define EACC(v, idx) do { s += ex2f(fmaf((v), L2E, -mb)); \
                          if ((v) == m) am = min(am, (idx)); } while (0)
        EACC(a0.x, ib +  0); EACC(a0.y, ib +  1); EACC(a0.z, ib +  2); EACC(a0.w, ib +  3);
        EACC(a1.x, ib + 16); EACC(a1.y, ib + 17); EACC(a1.z, ib + 18); EACC(a1.w, ib + 19);
        EACC(a2.x, ib + 32); EACC(a2.y, ib + 33); EACC(a2.z, ib + 34); EACC(a2.w, ib + 35);
        EACC(a3.x, ib + 48); EACC(a3.y, ib + 49); EACC(a3.z, ib + 50); EACC(a3.w, ib + 51);
        EACC(a4.x, ib + 64); EACC(a4.y, ib + 65); EACC(a4.z, ib + 66); EACC(a4.w, ib + 67);
        EACC(a5.x, ib + 80); EACC(a5.y, ib + 81); EACC(a5.z, ib + 82); EACC(a5.w, ib + 83);
        EACC(tl,   96 + q);
#undef EACC
        s  += __shfl_xor_sync(0xffffffffu, s, 1);
        s  += __shfl_xor_sync(0xffffffffu, s, 2);
        am  = min(am, __shfl_xor_sync(0xffffffffu, am, 1));
        am  = min(am, __shfl_xor_sync(0xffffffffu, am, 2));

        const float conf = 1.0f / s;          // = max softmax prob
        const int   lab  = labels[rowl];
        const float accv = (am == lab) ? 1.0f : 0.0f;
        const int   bin  = bin_of(conf);

        const bool mine = valid && ((bin & 3) == q);
        const int  slot = bin >> 2;
#pragma unroll
        for (int ss = 0; ss < 4; ss++) {
            if (mine && slot == ss) {
                cnt[ss]  += 1.0f;
                csum[ss] += conf;
                asum[ss] += accv;
            }
        }
    }

    // ---- combine the 8 groups within the warp (xor 4, 8, 16) ----
#pragma unroll
    for (int ss = 0; ss < 4; ss++) {
#pragma unroll
        for (int d = 4; d < 32; d <<= 1) {
            cnt[ss]  += __shfl_xor_sync(0xffffffffu, cnt[ss],  d);
            csum[ss] += __shfl_xor_sync(0xffffffffu, csum[ss], d);
            asum[ss] += __shfl_xor_sync(0xffffffffu, asum[ss], d);
        }
    }

    // ---- combine warps within the block ----
    __shared__ float sh[NCOL];
    if (tid < NCOL) sh[tid] = 0.0f;
    __syncthreads();
    if (lane < 4) {
#pragma unroll
        for (int ss = 0; ss < 4; ss++) {
            const int bin = q + 4 * ss;
            if (bin < NBINS) {
                atomicAdd(&sh[bin],             cnt[ss]);
                atomicAdd(&sh[NBINS + bin],     csum[ss]);
                atomicAdd(&sh[2 * NBINS + bin], asum[ss]);
            }
        }
    }
    __syncthreads();
    if (tid < NCOL)
        g_part[tid * NBLK + blockIdx.x] = (double)sh[tid];
}

// ---------------------------------------------------------------------------
// Generic fallback (any C): warp per row, two streaming passes (L1/L2 reuse).
// ---------------------------------------------------------------------------
__global__ __launch_bounds__(TPB)
void ece_pass1_generic(const float* __restrict__ logits,
                       const int*   __restrict__ labels,
                       int N, int C)
{
    const int tid  = threadIdx.x;
    const int lane = tid & 31;
    const int warpId = blockIdx.x * WPB + (tid >> 5);
    const int nWarps = NBLK * WPB;
    const float L2E = 1.4426950408889634f;

    __shared__ float sh[NCOL];
    if (tid < NCOL) sh[tid] = 0.0f;
    __syncthreads();

    for (int row = warpId; row < N; row += nWarps) {
        const float* rp = logits + (size_t)row * C;
        float m = -3.4e38f;
        int am = 0x7fffffff;
        for (int j = lane; j < C; j += 32) {
            float v = rp[j];
            if (v > m) { m = v; am = j; }
        }
#pragma unroll
        for (int d = 1; d < 32; d <<= 1) {
            float om = __shfl_xor_sync(0xffffffffu, m, d);
            int   oa = __shfl_xor_sync(0xffffffffu, am, d);
            if (om > m || (om == m && oa < am)) { m = om; am = oa; }
        }
        const float mb = m * L2E;
        float s = 0.f;
        for (int j = lane; j < C; j += 32)
            s += ex2f(fmaf(rp[j], L2E, -mb));
#pragma unroll
        for (int d = 1; d < 32; d <<= 1)
            s += __shfl_xor_sync(0xffffffffu, s, d);

        if (lane == 0) {
            const float conf = 1.0f / s;
            const float accv = (am == labels[row]) ? 1.0f : 0.0f;
            const int   bin  = bin_of(conf);
            atomicAdd(&sh[bin],             1.0f);
            atomicAdd(&sh[NBINS + bin],     conf);
            atomicAdd(&sh[2 * NBINS + bin], accv);
        }
    }
    __syncthreads();
    if (tid < NCOL)
        g_part[tid * NBLK + blockIdx.x] = (double)sh[tid];
}

// ---------------------------------------------------------------------------
// Reduce per-block partials: one block per column.
// ---------------------------------------------------------------------------
__global__ void ece_reduce()
{
    const int c = blockIdx.x;
    double s = 0.0;
    for (int b = threadIdx.x; b < NBLK; b += 256)
        s += g_part[c * NBLK + b];
    __shared__ double sd[256];
    sd[threadIdx.x] = s;
    __syncthreads();
    for (int o = 128; o > 0; o >>= 1) {
        if (threadIdx.x < o) sd[threadIdx.x] += sd[threadIdx.x + o];
        __syncthreads();
    }
    if (threadIdx.x == 0) g_red[c] = sd[0];
}

// ---------------------------------------------------------------------------
// Final ECE from 15 bins.
// ---------------------------------------------------------------------------
__global__ void ece_final(float* __restrict__ out, double n)
{
    const int l = threadIdx.x;
    double e = 0.0;
    if (l < NBINS) {
        const double c  = g_red[l];
        const double cs = g_red[NBINS + l];
        const double as = g_red[2 * NBINS + l];
        if (c > 0.0) {
            const double d = (c > 1.0) ? c : 1.0;
            e = fabs(cs / d - as / d) * (c / n);
        }
    }
#pragma unroll
    for (int o = 16; o > 0; o >>= 1)
        e += __shfl_xor_sync(0xffffffffu, e, o);
    if (l == 0) out[0] = (float)e;
}

extern "C" void kernel_launch(void* const* d_in, const int* in_sizes, int n_in,
                              void* d_out, int out_size)
{
    const float* logits = (const float*)d_in[0];
    const int*   labels = (const int*)d_in[1];
    const long long total = (long long)in_sizes[0];
    const int N = in_sizes[1];
    const int C = (int)(total / N);

    if (C == 100)
        ece_pass1_c100<<<NBLK, TPB>>>(logits, labels, N);
    else
        ece_pass1_generic<<<NBLK, TPB>>>(logits, labels, N, C);

    ece_reduce<<<NCOL, 256>>>();
    ece_final<<<1, 32>>>((float*)d_out, (double)N);
}

// round 2
// speedup vs baseline: 1.2717x; 1.2717x over previous
#include <cuda_runtime.h>
#include <cstdint>

#define NBLK  1024
#define TPB   256
#define WPB   8          // warps per block
#define NBINS 15
#define NCOL  45         // 15 counts, 15 conf sums, 15 acc sums
#define PAD   16         // spread accumulators across L2 lines (16 doubles = 128B)

// Global double accumulators (padded to one 128B line each) + nothing else.
__device__ double g_red[NCOL * PAD];

__device__ __forceinline__ float ex2f(float x) {
    float r; asm("ex2.approx.f32 %0, %1;" : "=f"(r) : "f"(x)); return r;
}

// ---------------------------------------------------------------------------
// Zero the accumulators (runs before pass1 each launch; graph-safe).
// ---------------------------------------------------------------------------
__global__ void ece_zero()
{
    if (threadIdx.x < NCOL * PAD) g_red[threadIdx.x] = 0.0;
}

// ---------------------------------------------------------------------------
// Main pass, specialized C=100. Layout: 4 lanes per row, 8 rows per warp.
// Lane (group g, sub q) loads float4 indices q, q+4, ..., q+20 (96 elems) plus
// scalar element 96+q  -> 25 floats per lane, row fully register-resident.
// acc via logits[row,label] == rowmax (no per-element argmax tracking).
// ---------------------------------------------------------------------------
__global__ __launch_bounds__(TPB, 4)
void ece_pass1_c100(const float* __restrict__ logits,
                    const int*   __restrict__ labels,
                    int N)
{
    const int tid  = threadIdx.x;
    const int lane = tid & 31;
    const int q    = lane & 3;          // sub-lane within row group
    const int grp  = lane >> 2;         // row group within warp (0..7)
    const int warpId = blockIdx.x * WPB + (tid >> 5);
    const int rowStride = NBLK * WPB * 8;   // 65536 rows per sweep

    const float L2E = 1.4426950408889634f;

    // Register histogram: lane q owns bins {q, q+4, q+8, q+12}
    float cnt[4]  = {0.f, 0.f, 0.f, 0.f};
    float csum[4] = {0.f, 0.f, 0.f, 0.f};
    float asum[4] = {0.f, 0.f, 0.f, 0.f};

#pragma unroll 1
    for (int base = warpId * 8; base < N; base += rowStride) {
        const int  row   = base + grp;
        const bool valid = (row < N);
        const int  rowl  = valid ? row : (N - 1);

        const float* rp   = logits + (size_t)rowl * 100;
        const float4* rp4 = reinterpret_cast<const float4*>(rp);

        // label + the label's logit (same cache lines as the row loads)
        const int   lab    = labels[rowl];
        const float labval = rp[lab];

        float4 a0 = rp4[q];
        float4 a1 = rp4[q + 4];
        float4 a2 = rp4[q + 8];
        float4 a3 = rp4[q + 12];
        float4 a4 = rp4[q + 16];
        float4 a5 = rp4[q + 20];
        float  tl = rp[96 + q];

        // ---- row max (balanced tree, then 2 shfl levels over the 4 lanes) ----
        float m0 = fmaxf(fmaxf(a0.x, a0.y), fmaxf(a0.z, a0.w));
        float m1 = fmaxf(fmaxf(a1.x, a1.y), fmaxf(a1.z, a1.w));
        float m2 = fmaxf(fmaxf(a2.x, a2.y), fmaxf(a2.z, a2.w));
        float m3 = fmaxf(fmaxf(a3.x, a3.y), fmaxf(a3.z, a3.w));
        float m4 = fmaxf(fmaxf(a4.x, a4.y), fmaxf(a4.z, a4.w));
        float m5 = fmaxf(fmaxf(a5.x, a5.y), fmaxf(a5.z, a5.w));
        float m  = fmaxf(fmaxf(fmaxf(m0, m1), fmaxf(m2, m3)),
                         fmaxf(fmaxf(m4, m5), tl));
        m = fmaxf(m, __shfl_xor_sync(0xffffffffu, m, 1));
        m = fmaxf(m, __shfl_xor_sync(0xffffffffu, m, 2));

        // ---- sum exp(v - m), 7 independent accumulators ----
        const float mb = m * L2E;
#define E(v) ex2f(fmaf((v), L2E, -mb))
        float s0 = (E(a0.x) + E(a0.y)) + (E(a0.z) + E(a0.w));
        float s1 = (E(a1.x) + E(a1.y)) + (E(a1.z) + E(a1.w));
        float s2 = (E(a2.x) + E(a2.y)) + (E(a2.z) + E(a2.w));
        float s3 = (E(a3.x) + E(a3.y)) + (E(a3.z) + E(a3.w));
        float s4 = (E(a4.x) + E(a4.y)) + (E(a4.z) + E(a4.w));
        float s5 = (E(a5.x) + E(a5.y)) + (E(a5.z) + E(a5.w));
        float s  = ((s0 + s1) + (s2 + s3)) + ((s4 + s5) + E(tl));
#undef E
        s += __shfl_xor_sync(0xffffffffu, s, 1);
        s += __shfl_xor_sync(0xffffffffu, s, 2);

        const float conf = 1.0f / s;                 // = max softmax prob
        const float accv = (labval == m) ? 1.0f : 0.0f;
        int bin = (int)(conf * 15.0f);
        bin = min(bin, NBINS - 1);

        const bool mine = valid && ((bin & 3) == q);
        const int  slot = bin >> 2;
#pragma unroll
        for (int ss = 0; ss < 4; ss++) {
            if (mine && slot == ss) {
                cnt[ss]  += 1.0f;
                csum[ss] += conf;
                asum[ss] += accv;
            }
        }
    }

    // ---- combine the 8 groups within the warp (xor 4, 8, 16) ----
#pragma unroll
    for (int ss = 0; ss < 4; ss++) {
#pragma unroll
        for (int d = 4; d < 32; d <<= 1) {
            cnt[ss]  += __shfl_xor_sync(0xffffffffu, cnt[ss],  d);
            csum[ss] += __shfl_xor_sync(0xffffffffu, csum[ss], d);
            asum[ss] += __shfl_xor_sync(0xffffffffu, asum[ss], d);
        }
    }

    // ---- combine warps within the block, then one atomic round per block ----
    __shared__ float sh[NCOL];
    if (tid < NCOL) sh[tid] = 0.0f;
    __syncthreads();
    if (lane < 4) {
#pragma unroll
        for (int ss = 0; ss < 4; ss++) {
            const int bin = q + 4 * ss;
            if (bin < NBINS) {
                atomicAdd(&sh[bin],             cnt[ss]);
                atomicAdd(&sh[NBINS + bin],     csum[ss]);
                atomicAdd(&sh[2 * NBINS + bin], asum[ss]);
            }
        }
    }
    __syncthreads();
    if (tid < NCOL)
        atomicAdd(&g_red[tid * PAD], (double)sh[tid]);
}

// ---------------------------------------------------------------------------
// Generic fallback (any C): warp per row.
// ---------------------------------------------------------------------------
__global__ __launch_bounds__(TPB)
void ece_pass1_generic(const float* __restrict__ logits,
                       const int*   __restrict__ labels,
                       int N, int C)
{
    const int tid  = threadIdx.x;
    const int lane = tid & 31;
    const int warpId = blockIdx.x * WPB + (tid >> 5);
    const int nWarps = NBLK * WPB;
    const float L2E = 1.4426950408889634f;

    __shared__ float sh[NCOL];
    if (tid < NCOL) sh[tid] = 0.0f;
    __syncthreads();

    for (int row = warpId; row < N; row += nWarps) {
        const float* rp = logits + (size_t)row * C;
        float m = -3.4e38f;
        int am = 0x7fffffff;
        for (int j = lane; j < C; j += 32) {
            float v = rp[j];
            if (v > m) { m = v; am = j; }
        }
#pragma unroll
        for (int d = 1; d < 32; d <<= 1) {
            float om = __shfl_xor_sync(0xffffffffu, m, d);
            int   oa = __shfl_xor_sync(0xffffffffu, am, d);
            if (om > m || (om == m && oa < am)) { m = om; am = oa; }
        }
        const float mb = m * L2E;
        float s = 0.f;
        for (int j = lane; j < C; j += 32)
            s += ex2f(fmaf(rp[j], L2E, -mb));
#pragma unroll
        for (int d = 1; d < 32; d <<= 1)
            s += __shfl_xor_sync(0xffffffffu, s, d);

        if (lane == 0) {
            const float conf = 1.0f / s;
            const float accv = (am == labels[row]) ? 1.0f : 0.0f;
            int bin = (int)(conf * 15.0f);
            bin = min(bin, NBINS - 1);
            atomicAdd(&sh[bin],             1.0f);
            atomicAdd(&sh[NBINS + bin],     conf);
            atomicAdd(&sh[2 * NBINS + bin], accv);
        }
    }
    __syncthreads();
    if (tid < NCOL)
        atomicAdd(&g_red[tid * PAD], (double)sh[tid]);
}

// ---------------------------------------------------------------------------
// Final ECE from 15 bins.
// ---------------------------------------------------------------------------
__global__ void ece_final(float* __restrict__ out, double n)
{
    const int l = threadIdx.x;
    double e = 0.0;
    if (l < NBINS) {
        const double c  = g_red[l * PAD];
        const double cs = g_red[(NBINS + l) * PAD];
        const double as = g_red[(2 * NBINS + l) * PAD];
        if (c > 0.0) {
            const double d = (c > 1.0) ? c : 1.0;
            e = fabs(cs / d - as / d) * (c / n);
        }
    }
#pragma unroll
    for (int o = 16; o > 0; o >>= 1)
        e += __shfl_xor_sync(0xffffffffu, e, o);
    if (l == 0) out[0] = (float)e;
}

extern "C" void kernel_launch(void* const* d_in, const int* in_sizes, int n_in,
                              void* d_out, int out_size)
{
    const float* logits = (const float*)d_in[0];
    const int*   labels = (const int*)d_in[1];
    const long long total = (long long)in_sizes[0];
    const int N = in_sizes[1];
    const int C = (int)(total / N);

    ece_zero<<<1, NCOL * PAD>>>();

    if (C == 100)
        ece_pass1_c100<<<NBLK, TPB>>>(logits, labels, N);
    else
        ece_pass1_generic<<<NBLK, TPB>>>(logits, labels, N, C);

    ece_final<<<1, 32>>>((float*)d_out, (double)N);
}

// round 3
// speedup vs baseline: 1.3473x; 1.0595x over previous
#include <cuda_runtime.h>
#include <cstdint>

#define NBLK  592        // 148 SMs x 4 blocks/SM -> exactly one wave
#define TPB   256
#define WPB   8          // warps per block
#define NBINS 15
#define NCOL  45         // 15 counts, 15 conf sums, 15 acc sums
#define PAD   16         // spread accumulators across L2 lines (16 doubles = 128B)

// Global double accumulators. Zero-initialized at module load; ece_final
// re-zeroes them after each consumption so every graph replay starts clean.
__device__ double g_red[NCOL * PAD];

__device__ __forceinline__ float ex2f(float x) {
    float r; asm("ex2.approx.f32 %0, %1;" : "=f"(r) : "f"(x)); return r;
}

// ---------------------------------------------------------------------------
// Main pass, specialized C=100. Layout: 4 lanes per row, 8 rows per warp.
// Lane (group g, sub q) loads float4 indices q, q+4, ..., q+20 (96 elems) plus
// scalar element 96+q  -> 25 floats per lane, row fully register-resident.
// acc via logits[row,label] == rowmax (no per-element argmax tracking).
// ---------------------------------------------------------------------------
__global__ __launch_bounds__(TPB, 4)
void ece_pass1_c100(const float* __restrict__ logits,
                    const int*   __restrict__ labels,
                    int N)
{
    const int tid  = threadIdx.x;
    const int lane = tid & 31;
    const int q    = lane & 3;          // sub-lane within row group
    const int grp  = lane >> 2;         // row group within warp (0..7)
    const int warpId = blockIdx.x * WPB + (tid >> 5);
    const int rowStride = NBLK * WPB * 8;   // rows per sweep

    const float L2E = 1.4426950408889634f;

    // Register histogram: lane q owns bins {q, q+4, q+8, q+12}
    float cnt[4]  = {0.f, 0.f, 0.f, 0.f};
    float csum[4] = {0.f, 0.f, 0.f, 0.f};
    float asum[4] = {0.f, 0.f, 0.f, 0.f};

#pragma unroll 1
    for (int base = warpId * 8; base < N; base += rowStride) {
        const int  row   = base + grp;
        const bool valid = (row < N);
        const int  rowl  = valid ? row : (N - 1);

        const float* rp   = logits + (size_t)rowl * 100;
        const float4* rp4 = reinterpret_cast<const float4*>(rp);

        // label + the label's logit (same cache lines as the row loads)
        const int   lab    = labels[rowl];
        const float labval = rp[lab];

        float4 a0 = rp4[q];
        float4 a1 = rp4[q + 4];
        float4 a2 = rp4[q + 8];
        float4 a3 = rp4[q + 12];
        float4 a4 = rp4[q + 16];
        float4 a5 = rp4[q + 20];
        float  tl = rp[96 + q];

        // ---- row max (balanced tree, then 2 shfl levels over the 4 lanes) ----
        float m0 = fmaxf(fmaxf(a0.x, a0.y), fmaxf(a0.z, a0.w));
        float m1 = fmaxf(fmaxf(a1.x, a1.y), fmaxf(a1.z, a1.w));
        float m2 = fmaxf(fmaxf(a2.x, a2.y), fmaxf(a2.z, a2.w));
        float m3 = fmaxf(fmaxf(a3.x, a3.y), fmaxf(a3.z, a3.w));
        float m4 = fmaxf(fmaxf(a4.x, a4.y), fmaxf(a4.z, a4.w));
        float m5 = fmaxf(fmaxf(a5.x, a5.y), fmaxf(a5.z, a5.w));
        float m  = fmaxf(fmaxf(fmaxf(m0, m1), fmaxf(m2, m3)),
                         fmaxf(fmaxf(m4, m5), tl));
        m = fmaxf(m, __shfl_xor_sync(0xffffffffu, m, 1));
        m = fmaxf(m, __shfl_xor_sync(0xffffffffu, m, 2));

        // ---- sum exp(v - m), independent accumulators ----
        const float mb = m * L2E;
#define E(v) ex2f(fmaf((v), L2E, -mb))
        float s0 = (E(a0.x) + E(a0.y)) + (E(a0.z) + E(a0.w));
        float s1 = (E(a1.x) + E(a1.y)) + (E(a1.z) + E(a1.w));
        float s2 = (E(a2.x) + E(a2.y)) + (E(a2.z) + E(a2.w));
        float s3 = (E(a3.x) + E(a3.y)) + (E(a3.z) + E(a3.w));
        float s4 = (E(a4.x) + E(a4.y)) + (E(a4.z) + E(a4.w));
        float s5 = (E(a5.x) + E(a5.y)) + (E(a5.z) + E(a5.w));
        float s  = ((s0 + s1) + (s2 + s3)) + ((s4 + s5) + E(tl));
#undef E
        s += __shfl_xor_sync(0xffffffffu, s, 1);
        s += __shfl_xor_sync(0xffffffffu, s, 2);

        const float conf = 1.0f / s;                 // = max softmax prob
        const float accv = (labval == m) ? 1.0f : 0.0f;
        int bin = (int)(conf * 15.0f);
        bin = min(bin, NBINS - 1);

        const bool mine = valid && ((bin & 3) == q);
        const int  slot = bin >> 2;
#pragma unroll
        for (int ss = 0; ss < 4; ss++) {
            if (mine && slot == ss) {
                cnt[ss]  += 1.0f;
                csum[ss] += conf;
                asum[ss] += accv;
            }
        }
    }

    // ---- combine the 8 groups within the warp (xor 4, 8, 16) ----
#pragma unroll
    for (int ss = 0; ss < 4; ss++) {
#pragma unroll
        for (int d = 4; d < 32; d <<= 1) {
            cnt[ss]  += __shfl_xor_sync(0xffffffffu, cnt[ss],  d);
            csum[ss] += __shfl_xor_sync(0xffffffffu, csum[ss], d);
            asum[ss] += __shfl_xor_sync(0xffffffffu, asum[ss], d);
        }
    }

    // ---- combine warps within the block, then one atomic round per block ----
    __shared__ float sh[NCOL];
    if (tid < NCOL) sh[tid] = 0.0f;
    __syncthreads();
    if (lane < 4) {
#pragma unroll
        for (int ss = 0; ss < 4; ss++) {
            const int bin = q + 4 * ss;
            if (bin < NBINS) {
                atomicAdd(&sh[bin],             cnt[ss]);
                atomicAdd(&sh[NBINS + bin],     csum[ss]);
                atomicAdd(&sh[2 * NBINS + bin], asum[ss]);
            }
        }
    }
    __syncthreads();
    if (tid < NCOL)
        atomicAdd(&g_red[tid * PAD], (double)sh[tid]);
}

// ---------------------------------------------------------------------------
// Generic fallback (any C): warp per row.
// ---------------------------------------------------------------------------
__global__ __launch_bounds__(TPB)
void ece_pass1_generic(const float* __restrict__ logits,
                       const int*   __restrict__ labels,
                       int N, int C)
{
    const int tid  = threadIdx.x;
    const int lane = tid & 31;
    const int warpId = blockIdx.x * WPB + (tid >> 5);
    const int nWarps = NBLK * WPB;
    const float L2E = 1.4426950408889634f;

    __shared__ float sh[NCOL];
    if (tid < NCOL) sh[tid] = 0.0f;
    __syncthreads();

    for (int row = warpId; row < N; row += nWarps) {
        const float* rp = logits + (size_t)row * C;
        float m = -3.4e38f;
        int am = 0x7fffffff;
        for (int j = lane; j < C; j += 32) {
            float v = rp[j];
            if (v > m) { m = v; am = j; }
        }
#pragma unroll
        for (int d = 1; d < 32; d <<= 1) {
            float om = __shfl_xor_sync(0xffffffffu, m, d);
            int   oa = __shfl_xor_sync(0xffffffffu, am, d);
            if (om > m || (om == m && oa < am)) { m = om; am = oa; }
        }
        const float mb = m * L2E;
        float s = 0.f;
        for (int j = lane; j < C; j += 32)
            s += ex2f(fmaf(rp[j], L2E, -mb));
#pragma unroll
        for (int d = 1; d < 32; d <<= 1)
            s += __shfl_xor_sync(0xffffffffu, s, d);

        if (lane == 0) {
            const float conf = 1.0f / s;
            const float accv = (am == labels[row]) ? 1.0f : 0.0f;
            int bin = (int)(conf * 15.0f);
            bin = min(bin, NBINS - 1);
            atomicAdd(&sh[bin],             1.0f);
            atomicAdd(&sh[NBINS + bin],     conf);
            atomicAdd(&sh[2 * NBINS + bin], accv);
        }
    }
    __syncthreads();
    if (tid < NCOL)
        atomicAdd(&g_red[tid * PAD], (double)sh[tid]);
}

// ---------------------------------------------------------------------------
// Final ECE from 15 bins; afterwards re-zero the accumulators so the next
// graph replay starts from a clean state (matches module-load zero-init).
// ---------------------------------------------------------------------------
__global__ void ece_final(float* __restrict__ out, double n)
{
    const int t = threadIdx.x;
    double e = 0.0;
    if (t < 32) {
        if (t < NBINS) {
            const double c  = g_red[t * PAD];
            const double cs = g_red[(NBINS + t) * PAD];
            const double as = g_red[(2 * NBINS + t) * PAD];
            if (c > 0.0) {
                const double d = (c > 1.0) ? c : 1.0;
                e = fabs(cs / d - as / d) * (c / n);
            }
        }
#pragma unroll
        for (int o = 16; o > 0; o >>= 1)
            e += __shfl_xor_sync(0xffffffffu, e, o);
    }
    __syncthreads();               // all reads of g_red complete
    for (int i = t; i < NCOL * PAD; i += blockDim.x)
        g_red[i] = 0.0;            // clean slate for next replay
    if (t == 0) out[0] = (float)e;
}

extern "C" void kernel_launch(void* const* d_in, const int* in_sizes, int n_in,
                              void* d_out, int out_size)
{
    const float* logits = (const float*)d_in[0];
    const int*   labels = (const int*)d_in[1];
    const long long total = (long long)in_sizes[0];
    const int N = in_sizes[1];
    const int C = (int)(total / N);

    if (C == 100)
        ece_pass1_c100<<<NBLK, TPB>>>(logits, labels, N);
    else
        ece_pass1_generic<<<NBLK, TPB>>>(logits, labels, N, C);

    ece_final<<<1, 256>>>((float*)d_out, (double)N);
}